// round 6
// baseline (speedup 1.0000x reference)
#include <cuda_runtime.h>
#include <math_constants.h>

#define BB 4
#define VV 4096
#define FF 64
#define SS 4
#define KN 39            // neighbours kept (K_NEIGHBOURS=40 includes self)
#define OUTF 64
#define TPB 128
#define BND_MAX 64
#define NB 512           // histogram bins
#define KBASE 760        // (u>>20) offset: covers biased exponents 95..158

// Scratch (device globals; no allocation allowed)
__device__ float g_coords[BB * VV * 4];     // (b, v, 4) — float4-aligned rows
__device__ float g_feats[BB * VV * FF];     // (b, v, 64)
__device__ float g_WoT[OUTF * 192];         // Wo transposed: [o][k]

// ---------------------------------------------------------------------------
// Kernel 1: coords = x@Ws + bs, feats = x@Wf + bf
// ---------------------------------------------------------------------------
__global__ void __launch_bounds__(64) prep_kernel(
    const float* __restrict__ x,
    const float* __restrict__ Wf, const float* __restrict__ bf,
    const float* __restrict__ Ws, const float* __restrict__ bs)
{
    const int vtx = blockIdx.x;        // 0 .. B*V-1
    const int f   = threadIdx.x;       // 0 .. 63
    __shared__ float sx[FF];
    sx[f] = x[vtx * FF + f];
    __syncthreads();

    float acc = bf[f];
#pragma unroll
    for (int k = 0; k < FF; ++k)
        acc = fmaf(sx[k], Wf[k * FF + f], acc);
    g_feats[vtx * FF + f] = acc;

    if (f < SS) {
        float c = bs[f];
#pragma unroll
        for (int k = 0; k < FF; ++k)
            c = fmaf(sx[k], Ws[k * SS + f], c);
        g_coords[vtx * 4 + f] = c;
    }
}

// Transpose Wo (192x64) into g_WoT (64x192) for vectorized GEMM reads.
__global__ void wot_kernel(const float* __restrict__ Wo)
{
    g_WoT[blockIdx.x * 192 + threadIdx.x] = Wo[threadIdx.x * OUTF + blockIdx.x];
}

__device__ __forceinline__ int d2_key(unsigned u)
{
    int p = (int)(u >> 20) - KBASE;
    p = max(p, 0);
    return min(p, NB - 1);
}

// ---------------------------------------------------------------------------
// Kernel 2: per-query kNN select (radix histogram over cached d2) + weighted
// max/mean aggregation + output GEMM + tanh. One block per query vertex.
// ---------------------------------------------------------------------------
__global__ void __launch_bounds__(TPB, 9) grav_kernel(
    const float* __restrict__ x,
    const float* __restrict__ bo,
    float* __restrict__ out)
{
    const int v    = blockIdx.x;       // vertex within batch
    const int b    = blockIdx.y;       // batch
    const int tid  = threadIdx.x;
    const int lane = tid & 31;
    const int base = b * VV;

    __shared__ float4 s_d2v[VV / 4];           // 16 KB (float4 view of d2)
    __shared__ unsigned s_hist[NB];            // 2 KB
    __shared__ float4 s_cat4[48];              // [xq(64) | max(64) | mean(64)]
    __shared__ int   s_nidx[KN + 1];
    __shared__ float s_nd2[KN + 1];
    __shared__ float s_nw[KN + 1];
    __shared__ float s_mx2[64], s_sm2[64], s_gemm[64];
    __shared__ unsigned long long s_bnd[BND_MAX];
    __shared__ unsigned long long s_red[4];
    __shared__ unsigned long long s_win;
    __shared__ int s_cdef, s_cbnd, s_bkey, s_c;
    __shared__ int s_wt[4];

    float* s_d2  = reinterpret_cast<float*>(s_d2v);
    float* s_cat = reinterpret_cast<float*>(s_cat4);

    const float4* cb = reinterpret_cast<const float4*>(g_coords) + base;
    const float4 cq = cb[v];

    if (tid < FF) s_cat[tid] = x[(base + v) * FF + tid];
    reinterpret_cast<uint4*>(s_hist)[tid] = make_uint4(0u, 0u, 0u, 0u);
    if (tid == 0) { s_cdef = 0; s_cbnd = 0; }
    __syncthreads();

    // ---- Pass 1: distances (cached in smem) + 512-bin histogram ----
    // Self distance forced to INF -> bin 511, auto-excluded downstream.
#pragma unroll 4
    for (int i = tid; i < VV; i += TPB) {
        float4 cu = cb[i];
        float dx = cq.x - cu.x, dy = cq.y - cu.y;
        float dz = cq.z - cu.z, dw = cq.w - cu.w;
        float d2 = fmaf(dx, dx, fmaf(dy, dy, fmaf(dz, dz, dw * dw)));
        if (i == v) d2 = CUDART_INF_F;
        s_d2[i] = d2;
        atomicAdd(&s_hist[d2_key(__float_as_uint(d2))], 1u);
    }
    __syncthreads();

    // ---- Parallel scan over 512 bins: crossing bin + prefix count ----
    {
        uint4 a = reinterpret_cast<uint4*>(s_hist)[tid];
        int h0 = (int)a.x, h1 = (int)a.y, h2 = (int)a.z, h3 = (int)a.w;
        int lsum = h0 + h1 + h2 + h3;
        int incl = lsum;
#pragma unroll
        for (int o = 1; o < 32; o <<= 1) {
            int n = __shfl_up_sync(0xffffffffu, incl, o);
            if (lane >= o) incl += n;
        }
        if (lane == 31) s_wt[tid >> 5] = incl;
        __syncthreads();
        int wprefix = 0;
        const int wid = tid >> 5;
        if (wid > 0) wprefix += s_wt[0];
        if (wid > 1) wprefix += s_wt[1];
        if (wid > 2) wprefix += s_wt[2];
        int excl = wprefix + incl - lsum;       // count before bin tid*4
        if (excl < KN && excl + lsum >= KN) {
            int cum = excl, bin = 4 * tid;
            if (cum + h0 < KN) { cum += h0; ++bin;
                if (cum + h1 < KN) { cum += h1; ++bin;
                    if (cum + h2 < KN) { cum += h2; ++bin; } } }
            s_bkey = bin; s_c = cum;
        }
        __syncthreads();
    }
    const int bkey = s_bkey;
    const int c = s_c;                          // definite count (< 39)
    // Clamp-exact uint thresholds for the boundary bin.
    const unsigned lo_u = (bkey == 0) ? 0u
                        : ((unsigned)(bkey + KBASE) << 20);
    const unsigned hi_u = (bkey == NB - 1) ? 0xFFFFFFFFu
                        : ((unsigned)(bkey + 1 + KBASE) << 20);

    // ---- Pass 2: gather definite + boundary (vectorized, 2 compares) ----
    for (int it = 0; it < VV / 4 / TPB; ++it) {
        int i4 = it * TPB + tid;
        float4 d4 = s_d2v[i4];
        int ib = i4 * 4;
#pragma unroll
        for (int e = 0; e < 4; ++e) {
            float dv = (e == 0) ? d4.x : (e == 1) ? d4.y : (e == 2) ? d4.z : d4.w;
            unsigned u = __float_as_uint(dv);
            if (u < hi_u) {
                if (u < lo_u) {
                    int pos = atomicAdd(&s_cdef, 1);
                    s_nidx[pos] = ib + e;
                    s_nd2[pos] = dv;
                } else if (ib + e != v) {
                    int pos = atomicAdd(&s_cbnd, 1);
                    if (pos < BND_MAX)
                        s_bnd[pos] = ((unsigned long long)u << 32)
                                     | (unsigned)(ib + e);
                }
            }
        }
    }
    __syncthreads();

    const int m = s_cbnd;
    const int r = KN - c;                       // boundary picks needed (>=1)

    if (m <= BND_MAX) {
        // Extract r smallest by (d2, idx) from the small boundary list.
        for (int j = 0; j < r; ++j) {
            unsigned long long lk = (tid < m) ? s_bnd[tid]
                                              : 0xFFFFFFFFFFFFFFFFULL;
#pragma unroll
            for (int o = 16; o > 0; o >>= 1) {
                unsigned long long oth = __shfl_down_sync(0xffffffffu, lk, o);
                lk = (oth < lk) ? oth : lk;
            }
            if (lane == 0) s_red[tid >> 5] = lk;
            __syncthreads();
            if (tid == 0) {
                unsigned long long w0 = s_red[0];
                if (s_red[1] < w0) w0 = s_red[1];
                if (s_red[2] < w0) w0 = s_red[2];
                if (s_red[3] < w0) w0 = s_red[3];
                s_win = w0;
                s_nidx[c + j] = (int)(w0 & 0xFFFFFFFFULL);
                s_nd2[c + j]  = __uint_as_float((unsigned)(w0 >> 32));
            }
            __syncthreads();
            if (tid < m && s_bnd[tid] == s_win)
                s_bnd[tid] = 0xFFFFFFFFFFFFFFFFULL;
            __syncthreads();
        }
    } else {
        // Degenerate fallback (massive tie bin): exact extraction over s_d2.
        for (int j = 0; j < r; ++j) {
            unsigned long long lk = 0xFFFFFFFFFFFFFFFFULL;
            for (int i = tid; i < VV; i += TPB) {
                unsigned u = __float_as_uint(s_d2[i]);
                if (u >= lo_u && u < hi_u && i != v) {
                    unsigned long long key =
                        ((unsigned long long)u << 32) | (unsigned)i;
                    if (key < lk) lk = key;
                }
            }
#pragma unroll
            for (int o = 16; o > 0; o >>= 1) {
                unsigned long long oth = __shfl_down_sync(0xffffffffu, lk, o);
                lk = (oth < lk) ? oth : lk;
            }
            if (lane == 0) s_red[tid >> 5] = lk;
            __syncthreads();
            if (tid == 0) {
                unsigned long long w0 = s_red[0];
                if (s_red[1] < w0) w0 = s_red[1];
                if (s_red[2] < w0) w0 = s_red[2];
                if (s_red[3] < w0) w0 = s_red[3];
                int widx = (int)(w0 & 0xFFFFFFFFULL);
                s_nidx[c + j] = widx;
                s_nd2[c + j]  = __uint_as_float((unsigned)(w0 >> 32));
                s_d2[widx] = __uint_as_float(0xFFFFFFFFu); // consumed marker
            }
            __syncthreads();
        }
    }

    // ---- Weights ----
    if (tid < KN)
        s_nw[tid] = expf(-10.0f * fabsf(s_nd2[tid]));
    __syncthreads();

    // ---- Weighted aggregation: max + mean over 39; constant trip counts ----
    {
        const float* fb = g_feats + (size_t)base * FF;
        const int f = tid & 63;
        const int half = tid >> 6;
        float mx = -CUDART_INF_F;
        float sm = 0.0f;
        if (half) {
#pragma unroll 4
            for (int j = 20; j < KN; ++j) {
                float val = fb[s_nidx[j] * FF + f] * s_nw[j];
                mx = fmaxf(mx, val);
                sm += val;
            }
            s_mx2[f] = mx; s_sm2[f] = sm;
        } else {
#pragma unroll 4
            for (int j = 0; j < 20; ++j) {
                float val = fb[s_nidx[j] * FF + f] * s_nw[j];
                mx = fmaxf(mx, val);
                sm += val;
            }
        }
        __syncthreads();
        if (!half) {
            mx = fmaxf(mx, s_mx2[f]);
            sm += s_sm2[f];
            s_cat[FF + f]       = mx;
            s_cat[2 * FF + f]   = sm * (1.0f / KN);
        }
        __syncthreads();
    }

    // ---- Output GEMM: s_cat (192) @ WoT (64x192) + bo, tanh.
    //      Vectorized float4 both sides; k split 96/96 across halves. ----
    {
        const int o = tid & 63;
        const int half = tid >> 6;
        const float4* wrow = reinterpret_cast<const float4*>(g_WoT) + o * 48;
        const int k0 = half * 24;
        float acc = 0.0f;
#pragma unroll
        for (int k4 = 0; k4 < 24; ++k4) {
            float4 a4 = s_cat4[k0 + k4];
            float4 w4 = wrow[k0 + k4];
            acc = fmaf(a4.x, w4.x, acc);
            acc = fmaf(a4.y, w4.y, acc);
            acc = fmaf(a4.z, w4.z, acc);
            acc = fmaf(a4.w, w4.w, acc);
        }
        if (half) s_gemm[o] = acc;
        __syncthreads();
        if (!half)
            out[(base + v) * OUTF + o] = tanhf(acc + s_gemm[o] + bo[o]);
    }
}

// ---------------------------------------------------------------------------
extern "C" void kernel_launch(void* const* d_in, const int* in_sizes, int n_in,
                              void* d_out, int out_size)
{
    const float* x  = (const float*)d_in[0];
    const float* Wf = (const float*)d_in[1];
    const float* bf = (const float*)d_in[2];
    const float* Ws = (const float*)d_in[3];
    const float* bs = (const float*)d_in[4];
    const float* Wo = (const float*)d_in[5];
    const float* bo = (const float*)d_in[6];
    float* out = (float*)d_out;

    wot_kernel<<<OUTF, 192>>>(Wo);
    prep_kernel<<<BB * VV, 64>>>(x, Wf, bf, Ws, bs);

    dim3 grid(VV, BB);
    grav_kernel<<<grid, TPB>>>(x, bo, out);
}

// round 8
// speedup vs baseline: 1.7384x; 1.7384x over previous
#include <cuda_runtime.h>
#include <math_constants.h>

#define BB 4
#define VV 4096
#define FF 64
#define SS 4
#define KN 39            // neighbours kept (K_NEIGHBOURS=40 includes self)
#define OUTF 64
#define TPB 128
#define BND_MAX 64
#define NB 512           // histogram bins
#define KBASE 760        // (u>>20) offset: covers biased exponents 95..158

// Scratch (device globals; no allocation allowed)
__device__ float g_coords[BB * VV * 4];     // (b, v, 4) — float4-aligned rows
__device__ float g_feats[BB * VV * FF];     // (b, v, 64)

// ---------------------------------------------------------------------------
// Kernel 1: coords = x@Ws + bs, feats = x@Wf + bf
// ---------------------------------------------------------------------------
__global__ void __launch_bounds__(64) prep_kernel(
    const float* __restrict__ x,
    const float* __restrict__ Wf, const float* __restrict__ bf,
    const float* __restrict__ Ws, const float* __restrict__ bs)
{
    const int vtx = blockIdx.x;        // 0 .. B*V-1
    const int f   = threadIdx.x;       // 0 .. 63
    __shared__ float sx[FF];
    sx[f] = x[vtx * FF + f];
    __syncthreads();

    float acc = bf[f];
#pragma unroll
    for (int k = 0; k < FF; ++k)
        acc = fmaf(sx[k], Wf[k * FF + f], acc);
    g_feats[vtx * FF + f] = acc;

    if (f < SS) {
        float c = bs[f];
#pragma unroll
        for (int k = 0; k < FF; ++k)
            c = fmaf(sx[k], Ws[k * SS + f], c);
        g_coords[vtx * 4 + f] = c;
    }
}

__device__ __forceinline__ int d2_key(unsigned u)
{
    int p = (int)(u >> 20) - KBASE;
    p = max(p, 0);
    return min(p, NB - 1);
}

// ---------------------------------------------------------------------------
// Kernel 2: per-query kNN select (radix histogram over cached d2) + weighted
// max/mean aggregation + output GEMM + tanh. One block per query vertex.
// ---------------------------------------------------------------------------
__global__ void __launch_bounds__(TPB, 10) grav_kernel(
    const float* __restrict__ x,
    const float* __restrict__ Wo, const float* __restrict__ bo,
    float* __restrict__ out)
{
    const int v    = blockIdx.x;       // vertex within batch
    const int b    = blockIdx.y;       // batch
    const int tid  = threadIdx.x;
    const int lane = tid & 31;
    const int base = b * VV;

    __shared__ float4 s_d2v[VV / 4];           // 16 KB (float4 view of d2)
    __shared__ unsigned s_hist[NB];            // 2 KB
    __shared__ float s_cat[192];               // [xq(64) | max(64) | mean(64)]
    __shared__ int   s_nidx[KN + 1];
    __shared__ float s_nd2[KN + 1];
    __shared__ float s_nw[KN + 1];
    __shared__ float s_mx2[64], s_sm2[64], s_gemm[64];
    __shared__ unsigned long long s_bnd[BND_MAX];
    __shared__ unsigned long long s_red[4];
    __shared__ unsigned long long s_win;
    __shared__ int s_cdef, s_cbnd, s_bkey, s_c;
    __shared__ int s_wt[4];

    float* s_d2 = reinterpret_cast<float*>(s_d2v);

    const float4* cb = reinterpret_cast<const float4*>(g_coords) + base;
    const float4 cq = cb[v];

    if (tid < FF) s_cat[tid] = x[(base + v) * FF + tid];
    reinterpret_cast<uint4*>(s_hist)[tid] = make_uint4(0u, 0u, 0u, 0u);
    if (tid == 0) { s_cdef = 0; s_cbnd = 0; }
    __syncthreads();

    // ---- Pass 1: distances (cached in smem) + 512-bin histogram.
    //      No self-check in the hot loop: self d2 == 0 exactly (bin 0);
    //      a single thread patches it out afterwards. ----
#pragma unroll 4
    for (int i = tid; i < VV; i += TPB) {
        float4 cu = cb[i];
        float dx = cq.x - cu.x, dy = cq.y - cu.y;
        float dz = cq.z - cu.z, dw = cq.w - cu.w;
        float d2 = fmaf(dx, dx, fmaf(dy, dy, fmaf(dz, dz, dw * dw)));
        s_d2[i] = d2;
        atomicAdd(&s_hist[d2_key(__float_as_uint(d2))], 1u);
    }
    __syncthreads();
    if (tid == 0) {
        s_hist[0]      -= 1u;                   // remove self (d2=0 -> bin 0)
        s_hist[NB - 1] += 1u;                   // park self in top bin
        s_d2[v] = CUDART_INF_F;
    }
    __syncthreads();

    // ---- Parallel scan over 512 bins: crossing bin + prefix count ----
    {
        uint4 a = reinterpret_cast<uint4*>(s_hist)[tid];
        int h0 = (int)a.x, h1 = (int)a.y, h2 = (int)a.z, h3 = (int)a.w;
        int lsum = h0 + h1 + h2 + h3;
        int incl = lsum;
#pragma unroll
        for (int o = 1; o < 32; o <<= 1) {
            int n = __shfl_up_sync(0xffffffffu, incl, o);
            if (lane >= o) incl += n;
        }
        if (lane == 31) s_wt[tid >> 5] = incl;
        __syncthreads();
        int wprefix = 0;
        const int wid = tid >> 5;
        if (wid > 0) wprefix += s_wt[0];
        if (wid > 1) wprefix += s_wt[1];
        if (wid > 2) wprefix += s_wt[2];
        int excl = wprefix + incl - lsum;       // count before bin tid*4
        if (excl < KN && excl + lsum >= KN) {
            int cum = excl, bin = 4 * tid;
            if (cum + h0 < KN) { cum += h0; ++bin;
                if (cum + h1 < KN) { cum += h1; ++bin;
                    if (cum + h2 < KN) { cum += h2; ++bin; } } }
            s_bkey = bin; s_c = cum;
        }
        __syncthreads();
    }
    const int bkey = s_bkey;
    const int c = s_c;                          // definite count (< 39)
    // Clamp-exact uint thresholds for the boundary bin.
    const unsigned lo_u = (bkey == 0) ? 0u
                        : ((unsigned)(bkey + KBASE) << 20);
    const unsigned hi_u = (bkey == NB - 1) ? 0xFFFFFFFFu
                        : ((unsigned)(bkey + 1 + KBASE) << 20);

    // ---- Pass 2: gather definite + boundary (vectorized, 2 compares) ----
    for (int it = 0; it < VV / 4 / TPB; ++it) {
        int i4 = it * TPB + tid;
        float4 d4 = s_d2v[i4];
        int ib = i4 * 4;
#pragma unroll
        for (int e = 0; e < 4; ++e) {
            float dv = (e == 0) ? d4.x : (e == 1) ? d4.y : (e == 2) ? d4.z : d4.w;
            unsigned u = __float_as_uint(dv);
            if (u < hi_u) {
                if (u < lo_u) {
                    int pos = atomicAdd(&s_cdef, 1);
                    s_nidx[pos] = ib + e;
                    s_nd2[pos] = dv;
                } else if (ib + e != v) {
                    int pos = atomicAdd(&s_cbnd, 1);
                    if (pos < BND_MAX)
                        s_bnd[pos] = ((unsigned long long)u << 32)
                                     | (unsigned)(ib + e);
                }
            }
        }
    }
    __syncthreads();

    const int m = s_cbnd;
    const int r = KN - c;                       // boundary picks needed (>=1)

    if (m <= BND_MAX) {
        // Extract r smallest by (d2, idx) from the small boundary list.
        for (int j = 0; j < r; ++j) {
            unsigned long long lk = (tid < m) ? s_bnd[tid]
                                              : 0xFFFFFFFFFFFFFFFFULL;
#pragma unroll
            for (int o = 16; o > 0; o >>= 1) {
                unsigned long long oth = __shfl_down_sync(0xffffffffu, lk, o);
                lk = (oth < lk) ? oth : lk;
            }
            if (lane == 0) s_red[tid >> 5] = lk;
            __syncthreads();
            if (tid == 0) {
                unsigned long long w0 = s_red[0];
                if (s_red[1] < w0) w0 = s_red[1];
                if (s_red[2] < w0) w0 = s_red[2];
                if (s_red[3] < w0) w0 = s_red[3];
                s_win = w0;
                s_nidx[c + j] = (int)(w0 & 0xFFFFFFFFULL);
                s_nd2[c + j]  = __uint_as_float((unsigned)(w0 >> 32));
            }
            __syncthreads();
            if (tid < m && s_bnd[tid] == s_win)
                s_bnd[tid] = 0xFFFFFFFFFFFFFFFFULL;
            __syncthreads();
        }
    } else {
        // Degenerate fallback (massive tie bin): exact extraction over s_d2.
        for (int j = 0; j < r; ++j) {
            unsigned long long lk = 0xFFFFFFFFFFFFFFFFULL;
            for (int i = tid; i < VV; i += TPB) {
                unsigned u = __float_as_uint(s_d2[i]);
                if (u >= lo_u && u < hi_u && i != v) {
                    unsigned long long key =
                        ((unsigned long long)u << 32) | (unsigned)i;
                    if (key < lk) lk = key;
                }
            }
#pragma unroll
            for (int o = 16; o > 0; o >>= 1) {
                unsigned long long oth = __shfl_down_sync(0xffffffffu, lk, o);
                lk = (oth < lk) ? oth : lk;
            }
            if (lane == 0) s_red[tid >> 5] = lk;
            __syncthreads();
            if (tid == 0) {
                unsigned long long w0 = s_red[0];
                if (s_red[1] < w0) w0 = s_red[1];
                if (s_red[2] < w0) w0 = s_red[2];
                if (s_red[3] < w0) w0 = s_red[3];
                int widx = (int)(w0 & 0xFFFFFFFFULL);
                s_nidx[c + j] = widx;
                s_nd2[c + j]  = __uint_as_float((unsigned)(w0 >> 32));
                s_d2[widx] = __uint_as_float(0xFFFFFFFFu); // consumed marker
            }
            __syncthreads();
        }
    }

    // ---- Weights ----
    if (tid < KN)
        s_nw[tid] = expf(-10.0f * fabsf(s_nd2[tid]));
    __syncthreads();

    // ---- Weighted aggregation: max + mean over 39; constant trip counts ----
    {
        const float* fb = g_feats + (size_t)base * FF;
        const int f = tid & 63;
        const int half = tid >> 6;
        float mx = -CUDART_INF_F;
        float sm = 0.0f;
        if (half) {
#pragma unroll 4
            for (int j = 20; j < KN; ++j) {
                float val = fb[s_nidx[j] * FF + f] * s_nw[j];
                mx = fmaxf(mx, val);
                sm += val;
            }
            s_mx2[f] = mx; s_sm2[f] = sm;
        } else {
#pragma unroll 4
            for (int j = 0; j < 20; ++j) {
                float val = fb[s_nidx[j] * FF + f] * s_nw[j];
                mx = fmaxf(mx, val);
                sm += val;
            }
        }
        __syncthreads();
        if (!half) {
            mx = fmaxf(mx, s_mx2[f]);
            sm += s_sm2[f];
            s_cat[FF + f]       = mx;
            s_cat[2 * FF + f]   = sm * (1.0f / KN);
        }
        __syncthreads();
    }

    // ---- Output GEMM: s_cat (192) @ Wo (192x64) + bo, tanh.
    //      Coalesced Wo reads (lanes consecutive in o); k split 96/96. ----
    {
        const int o = tid & 63;
        float acc = 0.0f;
        if (tid < 64) {
#pragma unroll
            for (int k = 0; k < 96; ++k)
                acc = fmaf(s_cat[k], Wo[k * OUTF + o], acc);
        } else {
#pragma unroll
            for (int k = 96; k < 192; ++k)
                acc = fmaf(s_cat[k], Wo[k * OUTF + o], acc);
            s_gemm[o] = acc;
        }
        __syncthreads();
        if (tid < 64)
            out[(base + v) * OUTF + o] = tanhf(acc + s_gemm[o] + bo[o]);
    }
}

// ---------------------------------------------------------------------------
extern "C" void kernel_launch(void* const* d_in, const int* in_sizes, int n_in,
                              void* d_out, int out_size)
{
    const float* x  = (const float*)d_in[0];
    const float* Wf = (const float*)d_in[1];
    const float* bf = (const float*)d_in[2];
    const float* Ws = (const float*)d_in[3];
    const float* bs = (const float*)d_in[4];
    const float* Wo = (const float*)d_in[5];
    const float* bo = (const float*)d_in[6];
    float* out = (float*)d_out;

    prep_kernel<<<BB * VV, 64>>>(x, Wf, bf, Ws, bs);

    dim3 grid(VV, BB);
    grav_kernel<<<grid, TPB>>>(x, Wo, bo, out);
}